// round 14
// baseline (speedup 1.0000x reference)
#include <cuda_runtime.h>
#include <math.h>

// ---------------- constants matching the reference ----------------
#define HH 121
#define WW 121
#define NE 225
#define NB 8
#define N_INTERP 200
#define RET_PER_DVA 280.0f
#define XRANGE0 (-15.0f)
#define YRANGE0 (-15.0f)
#define XYSTEP 0.25f
#define XLOWc (-4200.0f)
#define YLOWc (-4200.0f)
#define STEP_Xc (8400.0f/199.0f)
#define STEP_Yc (8400.0f/199.0f)
#define OD_OFF_Xc (15.5f*280.0f)
#define AMP_CUTOFF 0.25f
#define PIc 3.14159265358979323846f
#define TEMP1c (4.0f*PIc)
#define NEG_HALF_LOG2E (-0.7213475204444817f)   // -0.5*log2(e)
#define LOG2_045 (-1.1520030934450498f)         // log2(0.45)
#define CULL_T 22.0f                   // exp2(-22) ~ 2.4e-7 per dropped term

#define NPIX (HH*WW)
#define TILES_X 8
#define TILES_Y 8
#define EPB 29                         // electrodes per precompute block chunk

// per-(b,e) table:  e*2+0: (cx, cy2, R2cull, bright)   e*2+1: (c00, c01, c11, 2*c11)
__device__ float4 g_tab[NB][NE * 2];

__device__ __forceinline__ float ex2_fast(float x) {
    float r;
    asm("ex2.approx.ftz.f32 %0, %1;" : "=f"(r) : "f"(x));
    return r;
}

// ---------------- kernel A: per-electrode precompute ------------------
// grid (8 chunks, NB) x 32 threads; lane -> one electrode. MUFU-only chain.
__global__ __launch_bounds__(32) void precompute_kernel(
        const float* __restrict__ stim,
        const float* __restrict__ params,
        const float* __restrict__ elec_x,
        const float* __restrict__ elec_y,
        const float* __restrict__ slopes) {
    int b = blockIdx.y;
    int e = blockIdx.x * EPB + threadIdx.x;   // 8*29 = 232 >= 225
    if (threadIdx.x >= EPB || e >= NE) return;

    const float* P = params + b * 13;
    float rho = P[0], lam = P[1], osc = P[2];
    float a0 = P[3], a1 = P[4], a2 = P[5], a3 = P[6], a4 = P[7];
    float impx = P[8], impy = P[9], rot = P[10], lodx = P[11];
    float cr = __cosf(rot), sr = __sinf(rot);

    float exv = elec_x[e] * cr - elec_y[e] * sr + impx;
    float eyv = elec_x[e] * sr + elec_y[e] * cr + impy;
    float freq = stim[(b * NE + e) * 3 + 0];
    float amp  = stim[(b * NE + e) * 3 + 1];
    float pdur = stim[(b * NE + e) * 3 + 2];

    float cx = 0.f, cy2 = 0.f, R2c = -1.0f, bright = 0.f;   // R2c=-1 => never survives
    float c00 = 0.f, c01 = 0.f, c11 = 0.f;

    if (amp > AMP_CUTOFF) {
        float offx = lodx - OD_OFF_Xc;
        float qx = (exv - offx - XLOWc) * (1.0f / STEP_Xc);
        float qy = (eyv - YLOWc) * (1.0f / STEP_Yc);

        float fx = fminf(fmaxf(floorf(qx), 0.f), (float)(N_INTERP - 2));
        float fy = fminf(fmaxf(floorf(qy), 0.f), (float)(N_INTERP - 2));
        int ix = (int)fx, iy = (int)fy;
        float ax = fminf(fmaxf(qx - fx, 0.f), 1.f);
        float ay = fminf(fmaxf(qy - fy, 0.f), 1.f);
        float g00 = slopes[iy * N_INTERP + ix];
        float g01 = slopes[iy * N_INTERP + ix + 1];
        float g10 = slopes[(iy + 1) * N_INTERP + ix];
        float g11 = slopes[(iy + 1) * N_INTERP + ix + 1];
        float top = g00 + ax * (g01 - g00);
        float bot = g10 + ax * (g11 - g10);
        float th = top + ay * (bot - top);
        if (th < -PIc * 0.5f) th += PIc;
        th *= osc;

        float rs = fmaxf(rho * amp * a3, 1.0f);
        // 0.45^-a4 * pdur^a4 = exp2(a4*(log2(pdur) - log2(0.45)))
        float ls = lam * ex2_fast(a4 * (__log2f(pdur) - LOG2_045));
        ls = fminf(fmaxf(ls, 0.f), 0.99f);
        bright = a0 * ex2_fast(a1 * __log2f(fmaxf(amp, 1e-5f))) + a2 * freq;

        float t2 = sqrtf(1.0f - ls * ls);
        float sy = __fdividef(rs, TEMP1c * t2);
        float sx = rs * t2 * (1.0f / TEMP1c);
        float s = __sinf(th), c = __cosf(th);
        float cov00 = sx * c * c + sy * s * s;
        float cov01 = (sx - sy) * s * c;
        float cov11 = sx * s * s + sy * c * c;
        float det = cov00 * cov11 - cov01 * cov01;
        float rdet = __fdividef(1.0f, det);
        float inv00 = cov11 * rdet;
        float inv01 = -cov01 * rdet;
        float inv11 = cov00 * rdet;

        c00 = NEG_HALF_LOG2E * inv00;
        c01 = 2.0f * NEG_HALF_LOG2E * inv01;
        c11 = NEG_HALF_LOG2E * inv11;

        cx = (exv / RET_PER_DVA - XRANGE0) / XYSTEP;
        float cy = (float)HH - (eyv / RET_PER_DVA - YRANGE0) / XYSTEP;
        cy2 = 120.0f - cy;   // d1 = cy2 - r

        // cull radius^2: |t| >= lmin * dist^2; skip when lmin*dist^2 > CULL_T
        float trn = -(c00 + c11);
        float dQ  = c00 * c11 - 0.25f * c01 * c01;
        float disc = fmaxf(trn * trn - 4.0f * dQ, 0.f);
        float lmin = 0.5f * (trn - sqrtf(disc));
        R2c = __fdividef(CULL_T, fmaxf(lmin, 1e-20f));
    }

    g_tab[b][e * 2 + 0] = make_float4(cx, cy2, R2c, bright);
    g_tab[b][e * 2 + 1] = make_float4(c00, c01, c11, 2.0f * c11);
}

// ---------------- kernel B: cull + pixel loop + block reduction --------
// grid (8, 8, NB) = 512 blocks, block 256 (8 warps), 16x16 tile per block.
// Phase 1: lane e=tid loads table + cull test; block-wide deterministic
//          compaction of SURVIVORS into one shared list (ordered by e).
// Phase 2: warp w processes survivors s = w, w+8, ... (perfect balance);
//          warp covers the whole 16x16 tile, 8-row finite differences.
// Phase 3: block-local reduction of 8 warp-partials in fixed order.
__global__ __launch_bounds__(256) void mvg_kernel(float* __restrict__ out) {
    __shared__ float4 cA[NE];          // compacted survivors: cx, cy2, -, bright
    __shared__ float4 cB[NE];          // c00, c01, c11, 2*c11
    __shared__ float  spart[8][256];   // [warp][pixel-in-tile]
    __shared__ int    wcnt[8];
    __shared__ int    s_len;

    int b = blockIdx.z;
    int tid = threadIdx.x;
    int lane = tid & 31, w = tid >> 5;

    // tile center (block-uniform)
    float wcx = (float)(blockIdx.x * 16) + 7.5f;
    float wcy = (float)(blockIdx.y * 16) + 7.5f;

    // ---------------- phase 1: load + cull + block compaction ------------
    bool surv = false;
    float4 A, Bv;
    if (tid < NE) {
        A  = g_tab[b][tid * 2 + 0];
        Bv = g_tab[b][tid * 2 + 1];
        float dx = fmaxf(fabsf(wcx - A.x) - 7.5f, 0.f);
        float dy = fmaxf(fabsf(wcy - A.y) - 7.5f, 0.f);
        surv = (fmaf(dx, dx, dy * dy) <= A.z);   // R2c=-1 for inactive
    }
    unsigned mask = __ballot_sync(0xffffffffu, surv);
    if (lane == 0) wcnt[w] = __popc(mask);
    __syncthreads();
    int off = 0;
#pragma unroll
    for (int i = 0; i < 8; i++) off += (i < w) ? wcnt[i] : 0;
    if (tid == 0) {
        int tot = 0;
#pragma unroll
        for (int i = 0; i < 8; i++) tot += wcnt[i];
        s_len = tot;
    }
    if (surv) {
        int slot = off + __popc(mask & ((1u << lane) - 1u));
        cA[slot] = A;
        cB[slot] = Bv;
    }
    __syncthreads();
    int n = s_len;

    // ---------------- phase 2: survivor loop (16x16 tile, 8-row FD) ------
    int lx = lane & 15;
    int ly = lane >> 4;
    float cf  = (float)(blockIdx.x * 16 + lx);
    float rf0 = (float)(blockIdx.y * 16 + ly * 8);

    float acc[8];
#pragma unroll
    for (int i = 0; i < 8; i++) acc[i] = 0.f;

    for (int s = w; s < n; s += 8) {
        float4 SA = cA[s];             // cx, cy2, -, bright
        float4 SB = cB[s];             // c00, c01, c11, 2*c11

        float d0 = cf - SA.x;
        float k1 = SB.y * d0;          // c01*d0
        float k0 = (SB.x * d0) * d0;   // c00*d0^2
        float d1 = SA.y - rf0;

        float t   = fmaf(fmaf(SB.z, d1, k1), d1, k0);
        float dlt = fmaf(SB.z, fmaf(-2.0f, d1, 1.0f), -k1);

#pragma unroll
        for (int i = 0; i < 8; i++) {
            acc[i] = fmaf(SA.w, ex2_fast(t), acc[i]);
            t += dlt;
            dlt += SB.w;               // 2*c11
        }
    }

    // partials: pixel index in tile = (ly*8 + i)*16 + lx
    int pbase = ly * 128 + lx;
#pragma unroll
    for (int i = 0; i < 8; i++)
        spart[w][pbase + i * 16] = acc[i];
    __syncthreads();

    // ---------------- phase 3: block-local reduction ---------------------
    {
        // fixed warp order -> deterministic fp sum
        float v = spart[0][tid] + spart[1][tid] + spart[2][tid] + spart[3][tid]
                + spart[4][tid] + spart[5][tid] + spart[6][tid] + spart[7][tid];
        int r  = blockIdx.y * 16 + (tid >> 4);
        int cc = blockIdx.x * 16 + (tid & 15);
        if (r < HH && cc < WW)
            out[b * NPIX + r * WW + cc] = v;
    }
}

extern "C" void kernel_launch(void* const* d_in, const int* in_sizes, int n_in,
                              void* d_out, int out_size) {
    const float* stim   = (const float*)d_in[0];  // (8,225,3)
    const float* params = (const float*)d_in[1];  // (8,13)
    const float* ex     = (const float*)d_in[2];  // (1,225)
    const float* ey     = (const float*)d_in[3];  // (1,225)
    const float* slopes = (const float*)d_in[4];  // (200,200)
    // d_in[5] = pixelgrid: implied analytically, unused

    dim3 pgrid(8, NB);                              // 64 blocks x 32 threads
    precompute_kernel<<<pgrid, 32>>>(stim, params, ex, ey, slopes);

    dim3 grid(TILES_X, TILES_Y, NB);                // (8,8,8) x 256 threads
    mvg_kernel<<<grid, 256>>>((float*)d_out);
}